// round 8
// baseline (speedup 1.0000x reference)
#include <cuda_runtime.h>
#include <cuda_bf16.h>
#include <math.h>
#include <stdint.h>

// Problem constants
#define BB  8
#define MM  128
#define HID 256
#define NH  8
#define DD  32

// Scratch (device globals; allocation-free per harness rules)
__device__ float g_q[BB * MM * HID];                    // scaled q, [b][m][hid]
__device__ float g_v[BB * MM * HID];                    // [b][n][hid]
__device__ float g_nh[BB * MM * HID];                   // node_hidden [b][m][hid]
__device__ float g_k[(size_t)BB * MM * MM * HID];       // 128 MB, [b][m][n][hid]
__device__ float g_S[(size_t)BB * NH * MM * MM];        // scores [b][h][m][n]
__device__ float g_msg[(size_t)BB * NH * MM * MM];      // message [b][h][m][n]
// pre-split bf16 weights for the two tensor-core GEMMs
__device__ __nv_bfloat16 g_wkh[HID * HID], g_wkl[HID * HID];
__device__ __nv_bfloat16 g_weh[HID * HID], g_wel[HID * HID];

// mish(x) = x * tanh(softplus(x)) = x * (u^2-1)/(u^2+1), u = 1+e^x.
// Clamp x<=20 so u^2 stays finite (ratio is 1-4e-18 there already).
// x -> -inf: u -> 1, ratio -> 0, result 0 (correct limit).
__device__ __forceinline__ float mish_f(float x) {
    float e  = __expf(fminf(x, 20.f));
    float u  = 1.f + e;
    float u2 = u * u;
    return x * __fdividef(u2 - 1.f, u2 + 1.f);
}

__device__ __forceinline__ void mma16816(float c[4],
    uint32_t a0, uint32_t a1, uint32_t a2, uint32_t a3,
    uint32_t b0, uint32_t b1)
{
    asm volatile(
        "mma.sync.aligned.m16n8k16.row.col.f32.bf16.bf16.f32 "
        "{%0,%1,%2,%3}, {%4,%5,%6,%7}, {%8,%9}, {%0,%1,%2,%3};"
        : "+f"(c[0]), "+f"(c[1]), "+f"(c[2]), "+f"(c[3])
        : "r"(a0), "r"(a1), "r"(a2), "r"(a3), "r"(b0), "r"(b1));
}

__device__ __forceinline__ void cpasync16(void* smem_dst, const void* gsrc) {
    uint32_t s = (uint32_t)__cvta_generic_to_shared(smem_dst);
    asm volatile("cp.async.ca.shared.global [%0], [%1], 16;" :: "r"(s), "l"(gsrc));
}

// ---------------------------------------------------------------------------
// Weight pre-split: fp32 W -> (hi, lo) bf16 pair. 65536 elems per matrix.
// ---------------------------------------------------------------------------
__global__ void __launch_bounds__(256) convw_kernel(
    const float* __restrict__ Wk, const float* __restrict__ We)
{
    int idx = blockIdx.x * 256 + threadIdx.x;
    {
        float v = Wk[idx];
        __nv_bfloat16 h = __float2bfloat16_rn(v);
        g_wkh[idx] = h;
        g_wkl[idx] = __float2bfloat16_rn(v - __bfloat162float(h));
    }
    {
        float v = We[idx];
        __nv_bfloat16 h = __float2bfloat16_rn(v);
        g_weh[idx] = h;
        g_wel[idx] = __float2bfloat16_rn(v - __bfloat162float(h));
    }
}

// ---------------------------------------------------------------------------
// Tensor-core GEMM, error-compensated bf16 split (3 products ~ fp32 accuracy).
// C[r,o] = epi( sum_i A[r,i]*W[o,i] + bias[o] ),  A: Rx256 fp32.
// W passed pre-split as bf16 hi/lo, row-major [o][k].
// Block: 128x128 tile, 256 thr = 8 warps (2x4), warp tile 64x32, k-chunk 32.
// A chunks register-prefetched one iteration ahead (hides DRAM latency).
// PREMUL: A[r,i] *= msg[b, i/32, m, n]  (bx -> b,m ; tile row -> n).
// SFUSE (k projection only, requires !MISH): also emit
//   S[b, 4*by+wn, m, n] = sum_d q[b,m,...]*k[n,...] from the epilogue tile.
// ---------------------------------------------------------------------------
#define KST 40   // smem k-stride in bf16 (80B = 20 banks -> conflict-free frags)

template<bool PREMUL, bool MISH, bool SFUSE>
__global__ void __launch_bounds__(256, 2) mmagemm128(
    const float* __restrict__ A,
    const __nv_bfloat16* __restrict__ Whg,
    const __nv_bfloat16* __restrict__ Wlg,
    const float* __restrict__ bias,
    float* __restrict__ C)
{
    __shared__ __nv_bfloat16 Ah[128][KST], Al[128][KST];
    __shared__ __nv_bfloat16 Wh[128][KST], Wl[128][KST];
    __shared__ float ms[PREMUL ? 8 : 1][128];

    const int tid  = threadIdx.x;
    const int bx   = blockIdx.x;
    const size_t r0 = (size_t)bx * 128;
    const int o0   = blockIdx.y * 128;

    if (PREMUL) {
        const int b = bx >> 7, m = bx & 127;
        const float* mb = g_msg + ((size_t)b * 131072) + (size_t)m * 128;
        for (int idx = tid; idx < 1024; idx += 256) {
            int h = idx >> 7, n = idx & 127;
            ms[h][n] = mb[(size_t)h * 16384 + n];
        }
        __syncthreads();
    }

    const int lane = tid & 31;
    const int w    = tid >> 5;
    const int wm   = w >> 2;          // 0..1 -> m offset wm*64
    const int wn   = w & 3;           // 0..3 -> n offset wn*32

    // loader mapping: each thread stages one row-half (16 k) of A and of W
    const int arow  = tid >> 1;       // 0..127
    const int khalf = tid & 1;        // 0 / 1
    const float* Ag = A + (r0 + (size_t)arow) * 256 + khalf * 16;
    const __nv_bfloat16* Whp = Whg + (size_t)(o0 + arow) * 256 + khalf * 16;
    const __nv_bfloat16* Wlp = Wlg + (size_t)(o0 + arow) * 256 + khalf * 16;

    float acc[4][4][4];
#pragma unroll
    for (int i = 0; i < 4; i++)
#pragma unroll
        for (int j = 0; j < 4; j++)
#pragma unroll
            for (int t = 0; t < 4; t++) acc[i][j][t] = 0.f;

    // prefetch chunk 0 of A into registers
    float4 a_pre[4];
#pragma unroll
    for (int j = 0; j < 4; j++)
        a_pre[j] = reinterpret_cast<const float4*>(Ag)[j];

    for (int k0 = 0; k0 < 256; k0 += 32) {
        __syncthreads();   // previous compute done reading smem

        // ---- W chunk via cp.async (pre-split bf16, byte copy) ----
        {
            __nv_bfloat16* hd = &Wh[arow][khalf * 16];
            __nv_bfloat16* ld = &Wl[arow][khalf * 16];
            cpasync16(hd,     Whp + k0);
            cpasync16(hd + 8, Whp + k0 + 8);
            cpasync16(ld,     Wlp + k0);
            cpasync16(ld + 8, Wlp + k0 + 8);
            asm volatile("cp.async.commit_group;");
        }

        // ---- convert & store the prefetched A chunk (fp32 -> hi/lo bf16) ----
        {
            float f = 1.f;
            if (PREMUL) f = ms[k0 >> 5][arow];
#pragma unroll
            for (int j = 0; j < 4; j++) {
                float4 v4 = a_pre[j];
                float e[4] = {v4.x, v4.y, v4.z, v4.w};
                int kb = khalf * 16 + j * 4;
#pragma unroll
                for (int p = 0; p < 2; p++) {
                    float f0 = e[2 * p] * f, f1 = e[2 * p + 1] * f;
                    __nv_bfloat16 h0 = __float2bfloat16_rn(f0);
                    __nv_bfloat16 h1 = __float2bfloat16_rn(f1);
                    __nv_bfloat16 l0 = __float2bfloat16_rn(f0 - __bfloat162float(h0));
                    __nv_bfloat16 l1 = __float2bfloat16_rn(f1 - __bfloat162float(h1));
                    __nv_bfloat162 hp; hp.x = h0; hp.y = h1;
                    __nv_bfloat162 lp; lp.x = l0; lp.y = l1;
                    *reinterpret_cast<__nv_bfloat162*>(&Ah[arow][kb + 2 * p]) = hp;
                    *reinterpret_cast<__nv_bfloat162*>(&Al[arow][kb + 2 * p]) = lp;
                }
            }
        }

        // ---- issue A prefetch for next chunk; latency overlaps MMA phase ----
        if (k0 + 32 < 256) {
            const float4* apn = reinterpret_cast<const float4*>(Ag + k0 + 32);
#pragma unroll
            for (int j = 0; j < 4; j++) a_pre[j] = apn[j];
        }

        asm volatile("cp.async.wait_group 0;");
        __syncthreads();

        // ---- compute: 2 x k16 steps, 3 split-products each.
        //      B frags loaded once (16 regs); A frags per-fm (8 regs live) ----
#pragma unroll
        for (int ks = 0; ks < 32; ks += 16) {
            const int kk = (lane & 3) * 2;
            const int rb = wm * 64 + (lane >> 2);
            const int cb = wn * 32 + (lane >> 2);

            uint32_t bh[4][2], bl[4][2];
#pragma unroll
            for (int fn = 0; fn < 4; fn++) {
                int col = cb + fn * 8;
                bh[fn][0] = *reinterpret_cast<const uint32_t*>(&Wh[col][ks + kk]);
                bh[fn][1] = *reinterpret_cast<const uint32_t*>(&Wh[col][ks + kk + 8]);
                bl[fn][0] = *reinterpret_cast<const uint32_t*>(&Wl[col][ks + kk]);
                bl[fn][1] = *reinterpret_cast<const uint32_t*>(&Wl[col][ks + kk + 8]);
            }
#pragma unroll
            for (int fm = 0; fm < 4; fm++) {
                int row = rb + fm * 16;
                uint32_t a0 = *reinterpret_cast<const uint32_t*>(&Ah[row    ][ks + kk]);
                uint32_t a1 = *reinterpret_cast<const uint32_t*>(&Ah[row + 8][ks + kk]);
                uint32_t a2 = *reinterpret_cast<const uint32_t*>(&Ah[row    ][ks + kk + 8]);
                uint32_t a3 = *reinterpret_cast<const uint32_t*>(&Ah[row + 8][ks + kk + 8]);
                uint32_t l0 = *reinterpret_cast<const uint32_t*>(&Al[row    ][ks + kk]);
                uint32_t l1 = *reinterpret_cast<const uint32_t*>(&Al[row + 8][ks + kk]);
                uint32_t l2 = *reinterpret_cast<const uint32_t*>(&Al[row    ][ks + kk + 8]);
                uint32_t l3 = *reinterpret_cast<const uint32_t*>(&Al[row + 8][ks + kk + 8]);
#pragma unroll
                for (int fn = 0; fn < 4; fn++) {
                    mma16816(acc[fm][fn], a0, a1, a2, a3, bh[fn][0], bh[fn][1]);
                    mma16816(acc[fm][fn], l0, l1, l2, l3, bh[fn][0], bh[fn][1]);
                    mma16816(acc[fm][fn], a0, a1, a2, a3, bl[fn][0], bl[fn][1]);
                }
            }
        }
    }

    // ---- epilogue: bias, optional mish, store; optional fused scores ----
    float psA[4], psB[4];   // partial S for rows rb+fm*16 (+8)
    if (SFUSE) {
#pragma unroll
        for (int i = 0; i < 4; i++) { psA[i] = 0.f; psB[i] = 0.f; }
    }
    // q values for this thread's head/d slots (broadcast L1 hits)
    const float* qp = SFUSE ? (g_q + (size_t)bx * 256 + o0 + wn * 32) : nullptr;

#pragma unroll
    for (int fn = 0; fn < 4; fn++) {
        int col = o0 + wn * 32 + fn * 8 + (lane & 3) * 2;
        float b0 = bias[col], b1 = bias[col + 1];
        float q0 = 0.f, q1 = 0.f;
        if (SFUSE) {
            float2 qf = *reinterpret_cast<const float2*>(qp + fn * 8 + (lane & 3) * 2);
            q0 = qf.x; q1 = qf.y;
        }
#pragma unroll
        for (int fm = 0; fm < 4; fm++) {
            int row = wm * 64 + fm * 16 + (lane >> 2);
            float x0 = acc[fm][fn][0] + b0;
            float x1 = acc[fm][fn][1] + b1;
            float x2 = acc[fm][fn][2] + b0;
            float x3 = acc[fm][fn][3] + b1;
            if (SFUSE) {
                psA[fm] += x0 * q0 + x1 * q1;
                psB[fm] += x2 * q0 + x3 * q1;
            }
            if (MISH) { x0 = mish_f(x0); x1 = mish_f(x1); x2 = mish_f(x2); x3 = mish_f(x3); }
            *reinterpret_cast<float2*>(C + (r0 + row)     * 256 + col) = make_float2(x0, x1);
            *reinterpret_cast<float2*>(C + (r0 + row + 8) * 256 + col) = make_float2(x2, x3);
        }
    }

    if (SFUSE) {
        // reduce over the 4 lanes (lane&3 = fn-partner lanes) -> full 32-d dot
        const int b = bx >> 7, m = bx & 127;
        const int h = (o0 >> 5) + wn;
        float* Sout = g_S + (((size_t)(b * 8 + h)) * 128 + m) * 128;
#pragma unroll
        for (int fm = 0; fm < 4; fm++) {
            float a = psA[fm];
            a += __shfl_xor_sync(0xffffffffu, a, 1);
            a += __shfl_xor_sync(0xffffffffu, a, 2);
            float c = psB[fm];
            c += __shfl_xor_sync(0xffffffffu, c, 1);
            c += __shfl_xor_sync(0xffffffffu, c, 2);
            if ((lane & 3) == 0) {
                int n = wm * 64 + fm * 16 + (lane >> 2);
                Sout[n]     = a;
                Sout[n + 8] = c;
            }
        }
    }
}

// ---------------------------------------------------------------------------
// fp32 SGEMM for the small projections (1024x256 @ 256x256).
// ---------------------------------------------------------------------------
template<bool MISH>
__global__ void __launch_bounds__(256) sgemm128x128(
    const float* __restrict__ A,
    const float* __restrict__ W,
    const float* __restrict__ bias,
    float* __restrict__ C,
    float outScale)
{
    __shared__ float As[8][128];
    __shared__ float Bs[8][128];

    const int tid = threadIdx.x;
    const size_t r0 = (size_t)blockIdx.x * 128;
    const int o0 = blockIdx.y * 128;

    const int lrow = tid >> 1;
    const int lcol = (tid & 1) * 4;
    const float* Ap = A + (r0 + (size_t)lrow) * 256 + lcol;
    const float* Wp = W + (size_t)(o0 + lrow) * 256 + lcol;

    float acc[8][8];
#pragma unroll
    for (int i = 0; i < 8; i++)
#pragma unroll
        for (int j = 0; j < 8; j++) acc[i][j] = 0.f;

    const int ty = tid >> 4;
    const int tx = tid & 15;

    float4 av = *reinterpret_cast<const float4*>(Ap);
    float4 wv = *reinterpret_cast<const float4*>(Wp);

    for (int k0 = 0; k0 < 256; k0 += 8) {
        if (k0) __syncthreads();
        As[lcol + 0][lrow] = av.x; As[lcol + 1][lrow] = av.y;
        As[lcol + 2][lrow] = av.z; As[lcol + 3][lrow] = av.w;
        Bs[lcol + 0][lrow] = wv.x; Bs[lcol + 1][lrow] = wv.y;
        Bs[lcol + 2][lrow] = wv.z; Bs[lcol + 3][lrow] = wv.w;
        if (k0 + 8 < 256) {
            av = *reinterpret_cast<const float4*>(Ap + k0 + 8);
            wv = *reinterpret_cast<const float4*>(Wp + k0 + 8);
        }
        __syncthreads();
#pragma unroll
        for (int kk = 0; kk < 8; kk++) {
            float4 a0 = *reinterpret_cast<const float4*>(&As[kk][ty * 4]);
            float4 a1 = *reinterpret_cast<const float4*>(&As[kk][64 + ty * 4]);
            float4 b0 = *reinterpret_cast<const float4*>(&Bs[kk][tx * 4]);
            float4 b1 = *reinterpret_cast<const float4*>(&Bs[kk][64 + tx * 4]);
            float ar[8] = {a0.x, a0.y, a0.z, a0.w, a1.x, a1.y, a1.z, a1.w};
            float br[8] = {b0.x, b0.y, b0.z, b0.w, b1.x, b1.y, b1.z, b1.w};
#pragma unroll
            for (int i = 0; i < 8; i++)
#pragma unroll
                for (int j = 0; j < 8; j++)
                    acc[i][j] = fmaf(ar[i], br[j], acc[i][j]);
        }
    }

    float4 bb0 = *reinterpret_cast<const float4*>(bias + o0 + tx * 4);
    float4 bb1 = *reinterpret_cast<const float4*>(bias + o0 + 64 + tx * 4);
    float bcol[8] = {bb0.x, bb0.y, bb0.z, bb0.w, bb1.x, bb1.y, bb1.z, bb1.w};

#pragma unroll
    for (int i = 0; i < 8; i++) {
        int row = (i < 4) ? (ty * 4 + i) : (64 + ty * 4 + (i - 4));
        float* Crow = C + (r0 + (size_t)row) * 256 + o0;
#pragma unroll
        for (int jh = 0; jh < 2; jh++) {
            float vals[4];
#pragma unroll
            for (int j = 0; j < 4; j++) {
                float x = (acc[i][jh * 4 + j] + bcol[jh * 4 + j]) * outScale;
                if (MISH) x = mish_f(x);
                vals[j] = x;
            }
            *reinterpret_cast<float4*>(Crow + jh * 64 + tx * 4) =
                make_float4(vals[0], vals[1], vals[2], vals[3]);
        }
    }
}

// ---------------------------------------------------------------------------
// dual softmax + diag fix + distance decay -> message. one block per (b,h).
// msg[i,j] = (i!=j ? exp(Sij-rm_i-lam*d) : 0)*ri_i + exp(Sji-cm_i-lam*d)*ci_i
// (decay folded into the exponents: 2 fast exps instead of 3 exps + mul)
// ---------------------------------------------------------------------------
__global__ void __launch_bounds__(128) msg_kernel(
    const float* __restrict__ dist,
    const float* __restrict__ mask,
    const float* __restrict__ lam)
{
    const int bh = blockIdx.x;
    const int b = bh >> 3;
    __shared__ float rm[128], ri[128], cm[128], ci[128], msk[128];
    const int t = threadIdx.x;

    msk[t] = mask[b * 128 + t];
    __syncthreads();

    const float* Sb = g_S + (size_t)bh * 16384;

    {
        float mx = -INFINITY;
        for (int j = 0; j < 128; j++)
            if (msk[j] != 0.f) mx = fmaxf(mx, Sb[t * 128 + j]);
        float sm = 0.f;
        for (int j = 0; j < 128; j++)
            if (msk[j] != 0.f) sm += __expf(Sb[t * 128 + j] - mx);
        rm[t] = mx; ri[t] = 1.f / sm;
    }
    {
        float mx = -INFINITY;
        for (int j = 0; j < 128; j++)
            if (msk[j] != 0.f) mx = fmaxf(mx, Sb[j * 128 + t]);
        float sm = 0.f;
        for (int j = 0; j < 128; j++)
            if (msk[j] != 0.f) sm += __expf(Sb[j * 128 + t] - mx);
        cm[t] = mx; ci[t] = 1.f / sm;
    }
    __syncthreads();

    const float lambda = lam[0];
    float* Mb = g_msg + (size_t)bh * 16384;
    const float* Db = dist + (size_t)b * 16384;

    for (int idx = t; idx < 16384; idx += 128) {
        int i = idx >> 7, j = idx & 127;
        float out = 0.f;
        if (msk[j] != 0.f) {
            float ld = lambda * Db[i * 128 + j];
            float ia = __expf(Sb[j * 128 + i] - cm[i] - ld) * ci[i];
            float oa = (i == j) ? 0.f
                     : __expf(Sb[i * 128 + j] - rm[i] - ld) * ri[i];
            out = oa + ia;
        }
        Mb[idx] = out;
    }
}

// ---------------------------------------------------------------------------
// node_hidden[b,m,h*32+d] = sum_n msg[b,h,m,n] * v[b,n,h*32+d]
// ---------------------------------------------------------------------------
__global__ void __launch_bounds__(256) nh_kernel()
{
    const int bh = blockIdx.x;
    const int b = bh >> 3, h = bh & 7;
    __shared__ float vs[128][32];
    const int t = threadIdx.x;

    for (int idx = t; idx < 128 * 32; idx += 256) {
        int n = idx >> 5, d = idx & 31;
        vs[n][d] = g_v[((size_t)b * 128 + n) * 256 + h * 32 + d];
    }
    __syncthreads();

    const int d = t & 31, g = t >> 5;
#pragma unroll 4
    for (int it = 0; it < 16; it++) {
        int m = g * 16 + it;
        const float* mrow = g_msg + ((size_t)bh * 128 + m) * 128;
        float acc = 0.f;
#pragma unroll 8
        for (int n = 0; n < 128; n++) acc += mrow[n] * vs[n][d];
        g_nh[((size_t)b * 128 + m) * 256 + h * 32 + d] = acc;
    }
}

// ---------------------------------------------------------------------------
extern "C" void kernel_launch(void* const* d_in, const int* in_sizes, int n_in,
                              void* d_out, int out_size)
{
    const float* node = (const float*)d_in[0];
    const float* edge = (const float*)d_in[1];
    const float* dist = (const float*)d_in[2];
    const float* mask = (const float*)d_in[3];
    const float* lam  = (const float*)d_in[4];
    const float* Wq = (const float*)d_in[5];
    const float* bq = (const float*)d_in[6];
    const float* Wk = (const float*)d_in[7];
    const float* bk = (const float*)d_in[8];
    const float* Wv = (const float*)d_in[9];
    const float* bv = (const float*)d_in[10];
    const float* Wn = (const float*)d_in[11];
    const float* bn = (const float*)d_in[12];
    const float* We = (const float*)d_in[13];
    const float* be = (const float*)d_in[14];
    float* out = (float*)d_out;

    float *qb, *vb, *kb, *nhb;
    cudaGetSymbolAddress((void**)&qb, g_q);
    cudaGetSymbolAddress((void**)&vb, g_v);
    cudaGetSymbolAddress((void**)&kb, g_k);
    cudaGetSymbolAddress((void**)&nhb, g_nh);
    __nv_bfloat16 *wkh, *wkl, *weh, *wel;
    cudaGetSymbolAddress((void**)&wkh, g_wkh);
    cudaGetSymbolAddress((void**)&wkl, g_wkl);
    cudaGetSymbolAddress((void**)&weh, g_weh);
    cudaGetSymbolAddress((void**)&wel, g_wel);

    const float qscale = 0.17677669529663687f;   // 1/sqrt(32)

    // 0) pre-split big-GEMM weights into bf16 hi/lo
    convw_kernel<<<256, 256>>>(Wk, We);

    // 1) q (scaled) and v projections (fp32, small). q must precede k-GEMM (SFUSE reads g_q).
    sgemm128x128<false><<<dim3(8, 2), 256>>>(node, Wq, bq, qb, qscale);
    sgemm128x128<false><<<dim3(8, 2), 256>>>(node, Wv, bv, vb, 1.f);

    // 2) k projection + fused scores: 131072x256 @ 256x256 -> g_k, g_S
    mmagemm128<false, false, true><<<dim3(1024, 2), 256>>>(edge, wkh, wkl, bk, kb);

    // 3) dual softmax + diag fix + distance decay -> message
    msg_kernel<<<64, 128>>>(dist, mask, lam);

    // 4) node_hidden = message @ v
    nh_kernel<<<64, 256>>>();

    // 5) node output: mish(nh @ Wn^T + bn) -> out[0 : 262144)
    sgemm128x128<true><<<dim3(8, 2), 256>>>(nhb, Wn, bn, out, 1.f);

    // 6) edge output: mish((msg .* k) @ We^T + be) -> out[262144 : )
    mmagemm128<true, true, false><<<dim3(1024, 2), 256>>>(kb, weh, wel, be, out + 262144);
}

// round 13
// speedup vs baseline: 1.2294x; 1.2294x over previous
#include <cuda_runtime.h>
#include <cuda_bf16.h>
#include <math.h>
#include <stdint.h>

// Problem constants
#define BB  8
#define MM  128
#define HID 256
#define NH  8
#define DD  32

// Scratch (device globals; allocation-free per harness rules)
__device__ float g_q[BB * MM * HID];                    // scaled q, [b][m][hid]
__device__ float g_v[BB * MM * HID];                    // [b][n][hid]
__device__ float g_nh[BB * MM * HID];                   // node_hidden [b][m][hid]
__device__ float g_k[(size_t)BB * MM * MM * HID];       // 128 MB, [b][m][n][hid]
__device__ float g_S[(size_t)BB * NH * MM * MM];        // scores [b][h][m][n]
__device__ float g_msg[(size_t)BB * NH * MM * MM];      // message [b][h][m][n]
// pre-split bf16 weights (hi/lo) for all five GEMMs
__device__ __nv_bfloat16 g_wqh[HID * HID], g_wql[HID * HID];
__device__ __nv_bfloat16 g_wvh[HID * HID], g_wvl[HID * HID];
__device__ __nv_bfloat16 g_wkh[HID * HID], g_wkl[HID * HID];
__device__ __nv_bfloat16 g_wnh[HID * HID], g_wnl[HID * HID];
__device__ __nv_bfloat16 g_weh[HID * HID], g_wel[HID * HID];

// mish(x) = x * tanh(softplus(x)) = x * (u^2-1)/(u^2+1), u = 1+e^x.
__device__ __forceinline__ float mish_f(float x) {
    float e  = __expf(fminf(x, 20.f));
    float u  = 1.f + e;
    float u2 = u * u;
    return x * __fdividef(u2 - 1.f, u2 + 1.f);
}

__device__ __forceinline__ void mma16816(float c[4],
    uint32_t a0, uint32_t a1, uint32_t a2, uint32_t a3,
    uint32_t b0, uint32_t b1)
{
    asm volatile(
        "mma.sync.aligned.m16n8k16.row.col.f32.bf16.bf16.f32 "
        "{%0,%1,%2,%3}, {%4,%5,%6,%7}, {%8,%9}, {%0,%1,%2,%3};"
        : "+f"(c[0]), "+f"(c[1]), "+f"(c[2]), "+f"(c[3])
        : "r"(a0), "r"(a1), "r"(a2), "r"(a3), "r"(b0), "r"(b1));
}

__device__ __forceinline__ void ldsm4(uint32_t& r0, uint32_t& r1,
                                      uint32_t& r2, uint32_t& r3, uint32_t addr)
{
    asm volatile("ldmatrix.sync.aligned.m8n8.x4.shared.b16 {%0,%1,%2,%3}, [%4];"
                 : "=r"(r0), "=r"(r1), "=r"(r2), "=r"(r3) : "r"(addr));
}

__device__ __forceinline__ void cpasync16(void* smem_dst, const void* gsrc) {
    uint32_t s = (uint32_t)__cvta_generic_to_shared(smem_dst);
    asm volatile("cp.async.ca.shared.global [%0], [%1], 16;" :: "r"(s), "l"(gsrc));
}

// ---------------------------------------------------------------------------
// Weight pre-split: fp32 W -> (hi, lo) bf16 pairs for all 5 weight matrices.
// ---------------------------------------------------------------------------
__global__ void __launch_bounds__(256) convw_kernel(
    const float* __restrict__ Wq, const float* __restrict__ Wv,
    const float* __restrict__ Wk, const float* __restrict__ Wn,
    const float* __restrict__ We)
{
    int idx = blockIdx.x * 256 + threadIdx.x;
#define SPLIT1(SRC, DH, DL) { \
        float v = SRC[idx]; \
        __nv_bfloat16 h = __float2bfloat16_rn(v); \
        DH[idx] = h; DL[idx] = __float2bfloat16_rn(v - __bfloat162float(h)); }
    SPLIT1(Wq, g_wqh, g_wql)
    SPLIT1(Wv, g_wvh, g_wvl)
    SPLIT1(Wk, g_wkh, g_wkl)
    SPLIT1(Wn, g_wnh, g_wnl)
    SPLIT1(We, g_weh, g_wel)
#undef SPLIT1
}

// ---------------------------------------------------------------------------
// Tensor-core GEMM, error-compensated bf16 split (3 products ~ fp32 accuracy).
// C[r,o] = epi( (sum_i A[r,i]*W[o,i] + bias[o]) * outScale ),  A: Rx256 fp32.
// Fragments via ldmatrix; A chunks register-prefetched; W via cp.async.
// PREMUL: A[r,i] *= msg[b, i/32, m, n]. SFUSE: emit S from epilogue (k-GEMM).
// ---------------------------------------------------------------------------
#define KST 40   // smem k-stride in bf16 (80B = 16B-aligned rows, conflict-free)

template<bool PREMUL, bool MISH, bool SFUSE>
__global__ void __launch_bounds__(256, 2) mmagemm128(
    const float* __restrict__ A,
    const __nv_bfloat16* __restrict__ Whg,
    const __nv_bfloat16* __restrict__ Wlg,
    const float* __restrict__ bias,
    float* __restrict__ C,
    float outScale)
{
    __shared__ __align__(16) __nv_bfloat16 Ah[128][KST], Al[128][KST];
    __shared__ __align__(16) __nv_bfloat16 Wh[128][KST], Wl[128][KST];
    __shared__ float ms[PREMUL ? 8 : 1][128];

    const int tid  = threadIdx.x;
    const int bx   = blockIdx.x;
    const size_t r0 = (size_t)bx * 128;
    const int o0   = blockIdx.y * 128;

    if (PREMUL) {
        const int b = bx >> 7, m = bx & 127;
        const float* mb = g_msg + ((size_t)b * 131072) + (size_t)m * 128;
        for (int idx = tid; idx < 1024; idx += 256) {
            int h = idx >> 7, n = idx & 127;
            ms[h][n] = mb[(size_t)h * 16384 + n];
        }
        __syncthreads();
    }

    const int lane = tid & 31;
    const int w    = tid >> 5;
    const int wm   = w >> 2;          // 0..1 -> m offset wm*64
    const int wn   = w & 3;           // 0..3 -> n offset wn*32

    // ldmatrix per-lane source offsets (derived from m8n8.x4 matrix ordering)
    const int a_r = (lane & 7) + ((lane >> 3) & 1) * 8;   // row within 16
    const int a_k = ((lane >> 4) & 1) * 8;                // k offset 0/8
    const int b_c = (lane & 7) + ((lane >> 4) & 1) * 8;   // col within 16
    const int b_k = ((lane >> 3) & 1) * 8;                // k offset 0/8
    const uint32_t aBaseH = (uint32_t)__cvta_generic_to_shared(
        &Ah[wm * 64 + a_r][a_k]);
    const uint32_t aBaseL = (uint32_t)__cvta_generic_to_shared(
        &Al[wm * 64 + a_r][a_k]);
    const uint32_t bBaseH = (uint32_t)__cvta_generic_to_shared(
        &Wh[wn * 32 + b_c][b_k]);
    const uint32_t bBaseL = (uint32_t)__cvta_generic_to_shared(
        &Wl[wn * 32 + b_c][b_k]);

    // loader mapping: each thread stages one row-half (16 k) of A and of W
    const int arow  = tid >> 1;       // 0..127
    const int khalf = tid & 1;        // 0 / 1
    const float* Ag = A + (r0 + (size_t)arow) * 256 + khalf * 16;
    const __nv_bfloat16* Whp = Whg + (size_t)(o0 + arow) * 256 + khalf * 16;
    const __nv_bfloat16* Wlp = Wlg + (size_t)(o0 + arow) * 256 + khalf * 16;

    float acc[4][4][4];
#pragma unroll
    for (int i = 0; i < 4; i++)
#pragma unroll
        for (int j = 0; j < 4; j++)
#pragma unroll
            for (int t = 0; t < 4; t++) acc[i][j][t] = 0.f;

    // prefetch chunk 0 of A into registers
    float4 a_pre[4];
#pragma unroll
    for (int j = 0; j < 4; j++)
        a_pre[j] = reinterpret_cast<const float4*>(Ag)[j];

    for (int k0 = 0; k0 < 256; k0 += 32) {
        __syncthreads();   // previous compute done reading smem

        // ---- W chunk via cp.async (pre-split bf16, byte copy) ----
        {
            __nv_bfloat16* hd = &Wh[arow][khalf * 16];
            __nv_bfloat16* ld = &Wl[arow][khalf * 16];
            cpasync16(hd,     Whp + k0);
            cpasync16(hd + 8, Whp + k0 + 8);
            cpasync16(ld,     Wlp + k0);
            cpasync16(ld + 8, Wlp + k0 + 8);
            asm volatile("cp.async.commit_group;");
        }

        // ---- convert & store prefetched A chunk (fp32 -> hi/lo, STS.64) ----
        {
            float f = 1.f;
            if (PREMUL) f = ms[k0 >> 5][arow];
#pragma unroll
            for (int j = 0; j < 4; j++) {
                float4 v4 = a_pre[j];
                float e[4] = {v4.x * f, v4.y * f, v4.z * f, v4.w * f};
                int kb = khalf * 16 + j * 4;
                __nv_bfloat16 h0 = __float2bfloat16_rn(e[0]);
                __nv_bfloat16 h1 = __float2bfloat16_rn(e[1]);
                __nv_bfloat16 h2 = __float2bfloat16_rn(e[2]);
                __nv_bfloat16 h3 = __float2bfloat16_rn(e[3]);
                __nv_bfloat16 l0 = __float2bfloat16_rn(e[0] - __bfloat162float(h0));
                __nv_bfloat16 l1 = __float2bfloat16_rn(e[1] - __bfloat162float(h1));
                __nv_bfloat16 l2 = __float2bfloat16_rn(e[2] - __bfloat162float(h2));
                __nv_bfloat16 l3 = __float2bfloat16_rn(e[3] - __bfloat162float(h3));
                __nv_bfloat162 hp0; hp0.x = h0; hp0.y = h1;
                __nv_bfloat162 hp1; hp1.x = h2; hp1.y = h3;
                __nv_bfloat162 lp0; lp0.x = l0; lp0.y = l1;
                __nv_bfloat162 lp1; lp1.x = l2; lp1.y = l3;
                uint2 hu = make_uint2(*reinterpret_cast<uint32_t*>(&hp0),
                                      *reinterpret_cast<uint32_t*>(&hp1));
                uint2 lu = make_uint2(*reinterpret_cast<uint32_t*>(&lp0),
                                      *reinterpret_cast<uint32_t*>(&lp1));
                *reinterpret_cast<uint2*>(&Ah[arow][kb]) = hu;
                *reinterpret_cast<uint2*>(&Al[arow][kb]) = lu;
            }
        }

        // ---- issue A prefetch for next chunk; latency overlaps MMA phase ----
        if (k0 + 32 < 256) {
            const float4* apn = reinterpret_cast<const float4*>(Ag + k0 + 32);
#pragma unroll
            for (int j = 0; j < 4; j++) a_pre[j] = apn[j];
        }

        asm volatile("cp.async.wait_group 0;");
        __syncthreads();

        // ---- compute: 2 x k16 steps via ldmatrix, 3 split-products each ----
#pragma unroll
        for (int ks8 = 0; ks8 < 2; ks8++) {
            const uint32_t ko = (uint32_t)(ks8 * 16 * 2);   // byte offset of k16 step
            uint32_t bh[4][2], bl[4][2];
            ldsm4(bh[0][0], bh[0][1], bh[1][0], bh[1][1], bBaseH + ko);
            ldsm4(bh[2][0], bh[2][1], bh[3][0], bh[3][1], bBaseH + 16 * KST * 2 + ko);
            ldsm4(bl[0][0], bl[0][1], bl[1][0], bl[1][1], bBaseL + ko);
            ldsm4(bl[2][0], bl[2][1], bl[3][0], bl[3][1], bBaseL + 16 * KST * 2 + ko);
#pragma unroll
            for (int fm = 0; fm < 4; fm++) {
                const uint32_t fo = (uint32_t)(fm * 16 * KST * 2) + ko;
                uint32_t a0, a1, a2, a3, l0, l1, l2, l3;
                ldsm4(a0, a1, a2, a3, aBaseH + fo);
                ldsm4(l0, l1, l2, l3, aBaseL + fo);
#pragma unroll
                for (int fn = 0; fn < 4; fn++) {
                    mma16816(acc[fm][fn], a0, a1, a2, a3, bh[fn][0], bh[fn][1]);
                    mma16816(acc[fm][fn], l0, l1, l2, l3, bh[fn][0], bh[fn][1]);
                    mma16816(acc[fm][fn], a0, a1, a2, a3, bl[fn][0], bl[fn][1]);
                }
            }
        }
    }

    // ---- epilogue: bias, scale, optional mish, store; optional fused scores ----
    float psA[4], psB[4];
    if (SFUSE) {
#pragma unroll
        for (int i = 0; i < 4; i++) { psA[i] = 0.f; psB[i] = 0.f; }
    }
    const float* qp = SFUSE ? (g_q + (size_t)bx * 256 + o0 + wn * 32) : nullptr;

#pragma unroll
    for (int fn = 0; fn < 4; fn++) {
        int col = o0 + wn * 32 + fn * 8 + (lane & 3) * 2;
        float b0 = bias[col], b1 = bias[col + 1];
        float q0 = 0.f, q1 = 0.f;
        if (SFUSE) {
            float2 qf = *reinterpret_cast<const float2*>(qp + fn * 8 + (lane & 3) * 2);
            q0 = qf.x; q1 = qf.y;
        }
#pragma unroll
        for (int fm = 0; fm < 4; fm++) {
            int row = wm * 64 + fm * 16 + (lane >> 2);
            float x0 = (acc[fm][fn][0] + b0) * outScale;
            float x1 = (acc[fm][fn][1] + b1) * outScale;
            float x2 = (acc[fm][fn][2] + b0) * outScale;
            float x3 = (acc[fm][fn][3] + b1) * outScale;
            if (SFUSE) {
                psA[fm] += x0 * q0 + x1 * q1;
                psB[fm] += x2 * q0 + x3 * q1;
            }
            if (MISH) { x0 = mish_f(x0); x1 = mish_f(x1); x2 = mish_f(x2); x3 = mish_f(x3); }
            *reinterpret_cast<float2*>(C + (r0 + row)     * 256 + col) = make_float2(x0, x1);
            *reinterpret_cast<float2*>(C + (r0 + row + 8) * 256 + col) = make_float2(x2, x3);
        }
    }

    if (SFUSE) {
        const int b = bx >> 7, m = bx & 127;
        const int h = (o0 >> 5) + wn;
        float* Sout = g_S + (((size_t)(b * 8 + h)) * 128 + m) * 128;
#pragma unroll
        for (int fm = 0; fm < 4; fm++) {
            float a = psA[fm];
            a += __shfl_xor_sync(0xffffffffu, a, 1);
            a += __shfl_xor_sync(0xffffffffu, a, 2);
            float c = psB[fm];
            c += __shfl_xor_sync(0xffffffffu, c, 1);
            c += __shfl_xor_sync(0xffffffffu, c, 2);
            if ((lane & 3) == 0) {
                int n = wm * 64 + fm * 16 + (lane >> 2);
                Sout[n]     = a;
                Sout[n + 8] = c;
            }
        }
    }
}

// ---------------------------------------------------------------------------
// Fused: dual softmax + diag fix + distance decay -> message, THEN
// node_hidden = message @ v, all in one block per (b,h). 256 threads.
// (block's own global writes to g_msg are visible after __syncthreads)
// ---------------------------------------------------------------------------
__global__ void __launch_bounds__(256) msg_nh_kernel(
    const float* __restrict__ dist,
    const float* __restrict__ mask,
    const float* __restrict__ lam)
{
    const int bh = blockIdx.x;
    const int b = bh >> 3, h = bh & 7;
    __shared__ float rm[128], ri[128], cm[128], ci[128], msk[128];
    __shared__ float vs[128][32];
    const int t = threadIdx.x;
    const int r = t & 127;

    if (t < 128) msk[t] = mask[b * 128 + t];
    // stage v tile for the nh phase (overlaps stats loops)
    for (int idx = t; idx < 128 * 32; idx += 256) {
        int n = idx >> 5, d = idx & 31;
        vs[n][d] = g_v[((size_t)b * 128 + n) * 256 + h * 32 + d];
    }
    __syncthreads();

    const float* Sb = g_S + (size_t)bh * 16384;

    if (t < 128) {          // row stats: softmax over valid j of S[r, j]
        float mx = -INFINITY;
        for (int j = 0; j < 128; j++)
            if (msk[j] != 0.f) mx = fmaxf(mx, Sb[r * 128 + j]);
        float sm = 0.f;
        for (int j = 0; j < 128; j++)
            if (msk[j] != 0.f) sm += __expf(Sb[r * 128 + j] - mx);
        rm[r] = mx; ri[r] = 1.f / sm;
    } else {                // col stats: softmax over valid j of S[j, r]
        float mx = -INFINITY;
        for (int j = 0; j < 128; j++)
            if (msk[j] != 0.f) mx = fmaxf(mx, Sb[j * 128 + r]);
        float sm = 0.f;
        for (int j = 0; j < 128; j++)
            if (msk[j] != 0.f) sm += __expf(Sb[j * 128 + r] - mx);
        cm[r] = mx; ci[r] = 1.f / sm;
    }
    __syncthreads();

    const float lambda = lam[0];
    float* Mb = g_msg + (size_t)bh * 16384;
    const float* Db = dist + (size_t)b * 16384;

    for (int idx = t; idx < 16384; idx += 256) {
        int i = idx >> 7, j = idx & 127;
        float out = 0.f;
        if (msk[j] != 0.f) {
            float ld = lambda * Db[i * 128 + j];
            float ia = __expf(Sb[j * 128 + i] - cm[i] - ld) * ci[i];
            float oa = (i == j) ? 0.f
                     : __expf(Sb[i * 128 + j] - rm[i] - ld) * ri[i];
            out = oa + ia;
        }
        Mb[idx] = out;
    }
    __syncthreads();   // Mb fully written; visible to this block (L1-hot)

    // ---- nh phase: node_hidden[b,m,h*32+d] = sum_n Mb[m,n] * vs[n][d] ----
    const int d = t & 31, g = t >> 5;   // 8 groups of 32
#pragma unroll 4
    for (int it = 0; it < 16; it++) {
        int m = g * 16 + it;
        const float* mrow = Mb + (size_t)m * 128;
        float acc = 0.f;
#pragma unroll 8
        for (int n = 0; n < 128; n++) acc += mrow[n] * vs[n][d];
        g_nh[((size_t)b * 128 + m) * 256 + h * 32 + d] = acc;
    }
}

// ---------------------------------------------------------------------------
extern "C" void kernel_launch(void* const* d_in, const int* in_sizes, int n_in,
                              void* d_out, int out_size)
{
    const float* node = (const float*)d_in[0];
    const float* edge = (const float*)d_in[1];
    const float* dist = (const float*)d_in[2];
    const float* mask = (const float*)d_in[3];
    const float* lam  = (const float*)d_in[4];
    const float* Wq = (const float*)d_in[5];
    const float* bq = (const float*)d_in[6];
    const float* Wk = (const float*)d_in[7];
    const float* bk = (const float*)d_in[8];
    const float* Wv = (const float*)d_in[9];
    const float* bv = (const float*)d_in[10];
    const float* Wn = (const float*)d_in[11];
    const float* bn = (const float*)d_in[12];
    const float* We = (const float*)d_in[13];
    const float* be = (const float*)d_in[14];
    float* out = (float*)d_out;

    float *qb, *vb, *kb, *nhb;
    cudaGetSymbolAddress((void**)&qb, g_q);
    cudaGetSymbolAddress((void**)&vb, g_v);
    cudaGetSymbolAddress((void**)&kb, g_k);
    cudaGetSymbolAddress((void**)&nhb, g_nh);
    __nv_bfloat16 *wqh, *wql, *wvh, *wvl, *wkh, *wkl, *wnh, *wnl, *weh, *wel;
    cudaGetSymbolAddress((void**)&wqh, g_wqh);
    cudaGetSymbolAddress((void**)&wql, g_wql);
    cudaGetSymbolAddress((void**)&wvh, g_wvh);
    cudaGetSymbolAddress((void**)&wvl, g_wvl);
    cudaGetSymbolAddress((void**)&wkh, g_wkh);
    cudaGetSymbolAddress((void**)&wkl, g_wkl);
    cudaGetSymbolAddress((void**)&wnh, g_wnh);
    cudaGetSymbolAddress((void**)&wnl, g_wnl);
    cudaGetSymbolAddress((void**)&weh, g_weh);
    cudaGetSymbolAddress((void**)&wel, g_wel);

    const float qscale = 0.17677669529663687f;   // 1/sqrt(32)

    // 0) pre-split all weights into bf16 hi/lo
    convw_kernel<<<256, 256>>>(Wq, Wv, Wk, Wn, We);

    // 1) q (scaled) and v projections. q must precede k-GEMM (SFUSE reads g_q).
    mmagemm128<false, false, false><<<dim3(8, 2), 256>>>(node, wqh, wql, bq, qb, qscale);
    mmagemm128<false, false, false><<<dim3(8, 2), 256>>>(node, wvh, wvl, bv, vb, 1.f);

    // 2) k projection + fused scores: 131072x256 @ 256x256 -> g_k, g_S
    mmagemm128<false, false, true><<<dim3(1024, 2), 256>>>(edge, wkh, wkl, bk, kb, 1.f);

    // 3) dual softmax + diag fix + distance decay -> message; then nh = msg @ v
    msg_nh_kernel<<<64, 256>>>(dist, mask, lam);

    // 4) node output: mish(nh @ Wn^T + bn) -> out[0 : 262144)
    mmagemm128<false, true, false><<<dim3(8, 2), 256>>>(nhb, wnh, wnl, bn, out, 1.f);

    // 5) edge output: mish((msg .* k) @ We^T + be) -> out[262144 : )
    mmagemm128<true, true, false><<<dim3(1024, 2), 256>>>(kb, weh, wel, be, out + 262144, 1.f);
}

// round 14
// speedup vs baseline: 1.2533x; 1.0195x over previous
#include <cuda_runtime.h>
#include <cuda_bf16.h>
#include <math.h>
#include <stdint.h>

// Problem constants
#define BB  8
#define MM  128
#define HID 256
#define NH  8
#define DD  32

// Scratch (device globals; allocation-free per harness rules)
__device__ float g_q[BB * MM * HID];
__device__ float g_v[BB * MM * HID];
__device__ float g_nh[BB * MM * HID];
__device__ float g_k[(size_t)BB * MM * MM * HID];       // 128 MB
__device__ float g_S[(size_t)BB * NH * MM * MM];
__device__ float g_msg[(size_t)BB * NH * MM * MM];
// pre-split bf16 weights (hi/lo)
__device__ __nv_bfloat16 g_wqh[HID * HID], g_wql[HID * HID];
__device__ __nv_bfloat16 g_wvh[HID * HID], g_wvl[HID * HID];
__device__ __nv_bfloat16 g_wkh[HID * HID], g_wkl[HID * HID];
__device__ __nv_bfloat16 g_wnh[HID * HID], g_wnl[HID * HID];
__device__ __nv_bfloat16 g_weh[HID * HID], g_wel[HID * HID];

__device__ __forceinline__ float mish_f(float x) {
    float e  = __expf(fminf(x, 20.f));
    float u  = 1.f + e;
    float u2 = u * u;
    return x * __fdividef(u2 - 1.f, u2 + 1.f);
}

__device__ __forceinline__ void mma16816(float c[4],
    uint32_t a0, uint32_t a1, uint32_t a2, uint32_t a3,
    uint32_t b0, uint32_t b1)
{
    asm volatile(
        "mma.sync.aligned.m16n8k16.row.col.f32.bf16.bf16.f32 "
        "{%0,%1,%2,%3}, {%4,%5,%6,%7}, {%8,%9}, {%0,%1,%2,%3};"
        : "+f"(c[0]), "+f"(c[1]), "+f"(c[2]), "+f"(c[3])
        : "r"(a0), "r"(a1), "r"(a2), "r"(a3), "r"(b0), "r"(b1));
}

__device__ __forceinline__ void ldsm4(uint32_t& r0, uint32_t& r1,
                                      uint32_t& r2, uint32_t& r3, uint32_t addr)
{
    asm volatile("ldmatrix.sync.aligned.m8n8.x4.shared.b16 {%0,%1,%2,%3}, [%4];"
                 : "=r"(r0), "=r"(r1), "=r"(r2), "=r"(r3) : "r"(addr));
}

__device__ __forceinline__ void cpasync16(uint32_t smem_addr, const void* gsrc) {
    asm volatile("cp.async.ca.shared.global [%0], [%1], 16;"
                 :: "r"(smem_addr), "l"(gsrc));
}

// ---------------------------------------------------------------------------
__global__ void __launch_bounds__(256) convw_kernel(
    const float* __restrict__ Wq, const float* __restrict__ Wv,
    const float* __restrict__ Wk, const float* __restrict__ Wn,
    const float* __restrict__ We)
{
    int idx = blockIdx.x * 256 + threadIdx.x;
#define SPLIT1(SRC, DH, DL) { \
        float v = SRC[idx]; \
        __nv_bfloat16 h = __float2bfloat16_rn(v); \
        DH[idx] = h; DL[idx] = __float2bfloat16_rn(v - __bfloat162float(h)); }
    SPLIT1(Wq, g_wqh, g_wql)
    SPLIT1(Wv, g_wvh, g_wvl)
    SPLIT1(Wk, g_wkh, g_wkl)
    SPLIT1(Wn, g_wnh, g_wnl)
    SPLIT1(We, g_weh, g_wel)
#undef SPLIT1
}

// ---------------------------------------------------------------------------
// Tensor-core GEMM, bf16 split, DOUBLE-BUFFERED staging (stage i+1 || compute i).
// Dynamic smem: 2 stages x (Ah|Al|Wh|Wl) + ms. One barrier per chunk.
// ---------------------------------------------------------------------------
#define KST 40                       // k-stride in bf16 (80 B rows)
#define ARR_B (128 * KST * 2)        // 10240 B per array
#define STG_B (4 * ARR_B)            // 40960 B per stage
#define MS_OFF (2 * STG_B)           // 81920
#define SMEM_DYN (MS_OFF + 4096)     // 86016 B

template<bool PREMUL, bool MISH, bool SFUSE>
__global__ void __launch_bounds__(256, 2) mmagemm128(
    const float* __restrict__ A,
    const __nv_bfloat16* __restrict__ Whg,
    const __nv_bfloat16* __restrict__ Wlg,
    const float* __restrict__ bias,
    float* __restrict__ C,
    float outScale)
{
    extern __shared__ __align__(16) char smem[];
    const uint32_t sbase = (uint32_t)__cvta_generic_to_shared(smem);
    float* ms = reinterpret_cast<float*>(smem + MS_OFF);   // [8][128]

    const int tid  = threadIdx.x;
    const int bx   = blockIdx.x;
    const size_t r0 = (size_t)bx * 128;
    const int o0   = blockIdx.y * 128;

    if (PREMUL) {
        const int b = bx >> 7, m = bx & 127;
        const float* mb = g_msg + ((size_t)b * 131072) + (size_t)m * 128;
        for (int idx = tid; idx < 1024; idx += 256) {
            int h = idx >> 7, n = idx & 127;
            ms[h * 128 + n] = mb[(size_t)h * 16384 + n];
        }
        __syncthreads();
    }

    const int lane = tid & 31;
    const int w    = tid >> 5;
    const int wm   = w >> 2;
    const int wn   = w & 3;

    // ldmatrix per-lane source offsets
    const int a_r = (lane & 7) + ((lane >> 3) & 1) * 8;
    const int a_k = ((lane >> 4) & 1) * 8;
    const int b_c = (lane & 7) + ((lane >> 4) & 1) * 8;
    const int b_k = ((lane >> 3) & 1) * 8;
    // byte offsets within a stage
    const uint32_t aOffH = 0        + ((wm * 64 + a_r) * KST + a_k) * 2;
    const uint32_t aOffL = ARR_B    + ((wm * 64 + a_r) * KST + a_k) * 2;
    const uint32_t bOffH = 2*ARR_B  + ((wn * 32 + b_c) * KST + b_k) * 2;
    const uint32_t bOffL = 3*ARR_B  + ((wn * 32 + b_c) * KST + b_k) * 2;

    // loader mapping
    const int arow  = tid >> 1;
    const int khalf = tid & 1;
    const float* Ag = A + (r0 + (size_t)arow) * 256 + khalf * 16;
    const __nv_bfloat16* Whp = Whg + (size_t)(o0 + arow) * 256 + khalf * 16;
    const __nv_bfloat16* Wlp = Wlg + (size_t)(o0 + arow) * 256 + khalf * 16;
    // staging smem addresses (byte, within stage)
    const uint32_t stWh = 2*ARR_B + (arow * KST + khalf * 16) * 2;
    const uint32_t stWl = 3*ARR_B + (arow * KST + khalf * 16) * 2;
    const uint32_t stAh = 0       + (arow * KST + khalf * 16) * 2;
    const uint32_t stAl = ARR_B   + (arow * KST + khalf * 16) * 2;

    float acc[4][4][4];
#pragma unroll
    for (int i = 0; i < 4; i++)
#pragma unroll
        for (int j = 0; j < 4; j++)
#pragma unroll
            for (int t = 0; t < 4; t++) acc[i][j][t] = 0.f;

    float4 a_pre[4];
#pragma unroll
    for (int j = 0; j < 4; j++)
        a_pre[j] = reinterpret_cast<const float4*>(Ag)[j];

    // ---- staging helpers (as lambdas for stage-offset reuse) ----
    auto stageW = [&](int k0, uint32_t so) {
        cpasync16(sbase + so + stWh,      Whp + k0);
        cpasync16(sbase + so + stWh + 16, Whp + k0 + 8);
        cpasync16(sbase + so + stWl,      Wlp + k0);
        cpasync16(sbase + so + stWl + 16, Wlp + k0 + 8);
        asm volatile("cp.async.commit_group;");
    };
    auto stageA = [&](int chunk, uint32_t so) {
        float f = 1.f;
        if (PREMUL) f = ms[chunk * 128 + arow];
#pragma unroll
        for (int j = 0; j < 4; j++) {
            float4 v4 = a_pre[j];
            float e0 = v4.x * f, e1 = v4.y * f, e2 = v4.z * f, e3 = v4.w * f;
            __nv_bfloat16 h0 = __float2bfloat16_rn(e0);
            __nv_bfloat16 h1 = __float2bfloat16_rn(e1);
            __nv_bfloat16 h2 = __float2bfloat16_rn(e2);
            __nv_bfloat16 h3 = __float2bfloat16_rn(e3);
            __nv_bfloat16 l0 = __float2bfloat16_rn(e0 - __bfloat162float(h0));
            __nv_bfloat16 l1 = __float2bfloat16_rn(e1 - __bfloat162float(h1));
            __nv_bfloat16 l2 = __float2bfloat16_rn(e2 - __bfloat162float(h2));
            __nv_bfloat16 l3 = __float2bfloat16_rn(e3 - __bfloat162float(h3));
            __nv_bfloat162 hp0; hp0.x = h0; hp0.y = h1;
            __nv_bfloat162 hp1; hp1.x = h2; hp1.y = h3;
            __nv_bfloat162 lp0; lp0.x = l0; lp0.y = l1;
            __nv_bfloat162 lp1; lp1.x = l2; lp1.y = l3;
            uint2 hu = make_uint2(*reinterpret_cast<uint32_t*>(&hp0),
                                  *reinterpret_cast<uint32_t*>(&hp1));
            uint2 lu = make_uint2(*reinterpret_cast<uint32_t*>(&lp0),
                                  *reinterpret_cast<uint32_t*>(&lp1));
            *reinterpret_cast<uint2*>(smem + so + stAh + j * 8) = hu;
            *reinterpret_cast<uint2*>(smem + so + stAl + j * 8) = lu;
        }
    };

    // ---- prologue: fully stage chunk 0 into stage 0 ----
    stageW(0, 0);
    stageA(0, 0);
#pragma unroll
    for (int j = 0; j < 4; j++)
        a_pre[j] = reinterpret_cast<const float4*>(Ag + 32)[j];
    asm volatile("cp.async.wait_group 0;");
    __syncthreads();

    // ---- main loop: compute stage cur, stage chunk i+1 into nxt ----
#pragma unroll
    for (int i = 0; i < 8; i++) {
        const uint32_t soCur = (uint32_t)(i & 1) * STG_B;
        const uint32_t soNxt = soCur ^ STG_B;

        if (i < 7) {
            stageW((i + 1) * 32, soNxt);
            stageA(i + 1, soNxt);
            if (i < 6) {
                const float4* apn = reinterpret_cast<const float4*>(Ag + (i + 2) * 32);
#pragma unroll
                for (int j = 0; j < 4; j++) a_pre[j] = apn[j];
            }
        }

        // compute on soCur (overlaps the STS/cp.async above in the L1 pipe)
#pragma unroll
        for (int ks8 = 0; ks8 < 2; ks8++) {
            const uint32_t ko = (uint32_t)(ks8 * 32);   // 16 bf16 = 32 B
            uint32_t bh[4][2], bl[4][2];
            ldsm4(bh[0][0], bh[0][1], bh[1][0], bh[1][1], sbase + soCur + bOffH + ko);
            ldsm4(bh[2][0], bh[2][1], bh[3][0], bh[3][1], sbase + soCur + bOffH + 16 * KST * 2 + ko);
            ldsm4(bl[0][0], bl[0][1], bl[1][0], bl[1][1], sbase + soCur + bOffL + ko);
            ldsm4(bl[2][0], bl[2][1], bl[3][0], bl[3][1], sbase + soCur + bOffL + 16 * KST * 2 + ko);
#pragma unroll
            for (int fm = 0; fm < 4; fm++) {
                const uint32_t fo = (uint32_t)(fm * 16 * KST * 2) + ko;
                uint32_t a0, a1, a2, a3, l0, l1, l2, l3;
                ldsm4(a0, a1, a2, a3, sbase + soCur + aOffH + fo);
                ldsm4(l0, l1, l2, l3, sbase + soCur + aOffL + fo);
#pragma unroll
                for (int fn = 0; fn < 4; fn++) {
                    mma16816(acc[fm][fn], a0, a1, a2, a3, bh[fn][0], bh[fn][1]);
                    mma16816(acc[fm][fn], l0, l1, l2, l3, bh[fn][0], bh[fn][1]);
                    mma16816(acc[fm][fn], a0, a1, a2, a3, bl[fn][0], bl[fn][1]);
                }
            }
        }

        if (i < 7) {
            asm volatile("cp.async.wait_group 0;");
            __syncthreads();
        }
    }

    // ---- epilogue: bias, scale, optional mish, store; optional fused scores ----
    float psA[4], psB[4];
    if (SFUSE) {
#pragma unroll
        for (int i = 0; i < 4; i++) { psA[i] = 0.f; psB[i] = 0.f; }
    }
    const float* qp = SFUSE ? (g_q + (size_t)bx * 256 + o0 + wn * 32) : nullptr;

#pragma unroll
    for (int fn = 0; fn < 4; fn++) {
        int col = o0 + wn * 32 + fn * 8 + (lane & 3) * 2;
        float b0 = bias[col], b1 = bias[col + 1];
        float q0 = 0.f, q1 = 0.f;
        if (SFUSE) {
            float2 qf = *reinterpret_cast<const float2*>(qp + fn * 8 + (lane & 3) * 2);
            q0 = qf.x; q1 = qf.y;
        }
#pragma unroll
        for (int fm = 0; fm < 4; fm++) {
            int row = wm * 64 + fm * 16 + (lane >> 2);
            float x0 = (acc[fm][fn][0] + b0) * outScale;
            float x1 = (acc[fm][fn][1] + b1) * outScale;
            float x2 = (acc[fm][fn][2] + b0) * outScale;
            float x3 = (acc[fm][fn][3] + b1) * outScale;
            if (SFUSE) {
                psA[fm] += x0 * q0 + x1 * q1;
                psB[fm] += x2 * q0 + x3 * q1;
            }
            if (MISH) { x0 = mish_f(x0); x1 = mish_f(x1); x2 = mish_f(x2); x3 = mish_f(x3); }
            *reinterpret_cast<float2*>(C + (r0 + row)     * 256 + col) = make_float2(x0, x1);
            *reinterpret_cast<float2*>(C + (r0 + row + 8) * 256 + col) = make_float2(x2, x3);
        }
    }

    if (SFUSE) {
        const int b = bx >> 7, m = bx & 127;
        const int h = (o0 >> 5) + wn;
        float* Sout = g_S + (((size_t)(b * 8 + h)) * 128 + m) * 128;
#pragma unroll
        for (int fm = 0; fm < 4; fm++) {
            float a = psA[fm];
            a += __shfl_xor_sync(0xffffffffu, a, 1);
            a += __shfl_xor_sync(0xffffffffu, a, 2);
            float c = psB[fm];
            c += __shfl_xor_sync(0xffffffffu, c, 1);
            c += __shfl_xor_sync(0xffffffffu, c, 2);
            if ((lane & 3) == 0) {
                int n = wm * 64 + fm * 16 + (lane >> 2);
                Sout[n]     = a;
                Sout[n + 8] = c;
            }
        }
    }
}

// ---------------------------------------------------------------------------
// Fused: dual softmax + diag fix + distance decay -> message, then nh = msg @ v
// ---------------------------------------------------------------------------
__global__ void __launch_bounds__(256) msg_nh_kernel(
    const float* __restrict__ dist,
    const float* __restrict__ mask,
    const float* __restrict__ lam)
{
    const int bh = blockIdx.x;
    const int b = bh >> 3, h = bh & 7;
    __shared__ float rm[128], ri[128], cm[128], ci[128], msk[128];
    __shared__ float vs[128][32];
    const int t = threadIdx.x;
    const int r = t & 127;

    if (t < 128) msk[t] = mask[b * 128 + t];
    for (int idx = t; idx < 128 * 32; idx += 256) {
        int n = idx >> 5, d = idx & 31;
        vs[n][d] = g_v[((size_t)b * 128 + n) * 256 + h * 32 + d];
    }
    __syncthreads();

    const float* Sb = g_S + (size_t)bh * 16384;

    if (t < 128) {
        float mx = -INFINITY;
        for (int j = 0; j < 128; j++)
            if (msk[j] != 0.f) mx = fmaxf(mx, Sb[r * 128 + j]);
        float sm = 0.f;
        for (int j = 0; j < 128; j++)
            if (msk[j] != 0.f) sm += __expf(Sb[r * 128 + j] - mx);
        rm[r] = mx; ri[r] = 1.f / sm;
    } else {
        float mx = -INFINITY;
        for (int j = 0; j < 128; j++)
            if (msk[j] != 0.f) mx = fmaxf(mx, Sb[j * 128 + r]);
        float sm = 0.f;
        for (int j = 0; j < 128; j++)
            if (msk[j] != 0.f) sm += __expf(Sb[j * 128 + r] - mx);
        cm[r] = mx; ci[r] = 1.f / sm;
    }
    __syncthreads();

    const float lambda = lam[0];
    float* Mb = g_msg + (size_t)bh * 16384;
    const float* Db = dist + (size_t)b * 16384;

    for (int idx = t; idx < 16384; idx += 256) {
        int i = idx >> 7, j = idx & 127;
        float out = 0.f;
        if (msk[j] != 0.f) {
            float ld = lambda * Db[i * 128 + j];
            float ia = __expf(Sb[j * 128 + i] - cm[i] - ld) * ci[i];
            float oa = (i == j) ? 0.f
                     : __expf(Sb[i * 128 + j] - rm[i] - ld) * ri[i];
            out = oa + ia;
        }
        Mb[idx] = out;
    }
    __syncthreads();

    const int d = t & 31, g = t >> 5;
#pragma unroll 4
    for (int it = 0; it < 16; it++) {
        int m = g * 16 + it;
        const float* mrow = Mb + (size_t)m * 128;
        float acc = 0.f;
#pragma unroll 8
        for (int n = 0; n < 128; n++) acc += mrow[n] * vs[n][d];
        g_nh[((size_t)b * 128 + m) * 256 + h * 32 + d] = acc;
    }
}

// ---------------------------------------------------------------------------
extern "C" void kernel_launch(void* const* d_in, const int* in_sizes, int n_in,
                              void* d_out, int out_size)
{
    const float* node = (const float*)d_in[0];
    const float* edge = (const float*)d_in[1];
    const float* dist = (const float*)d_in[2];
    const float* mask = (const float*)d_in[3];
    const float* lam  = (const float*)d_in[4];
    const float* Wq = (const float*)d_in[5];
    const float* bq = (const float*)d_in[6];
    const float* Wk = (const float*)d_in[7];
    const float* bk = (const float*)d_in[8];
    const float* Wv = (const float*)d_in[9];
    const float* bv = (const float*)d_in[10];
    const float* Wn = (const float*)d_in[11];
    const float* bn = (const float*)d_in[12];
    const float* We = (const float*)d_in[13];
    const float* be = (const float*)d_in[14];
    float* out = (float*)d_out;

    float *qb, *vb, *kb, *nhb;
    cudaGetSymbolAddress((void**)&qb, g_q);
    cudaGetSymbolAddress((void**)&vb, g_v);
    cudaGetSymbolAddress((void**)&kb, g_k);
    cudaGetSymbolAddress((void**)&nhb, g_nh);
    __nv_bfloat16 *wqh, *wql, *wvh, *wvl, *wkh, *wkl, *wnh, *wnl, *weh, *wel;
    cudaGetSymbolAddress((void**)&wqh, g_wqh);
    cudaGetSymbolAddress((void**)&wql, g_wql);
    cudaGetSymbolAddress((void**)&wvh, g_wvh);
    cudaGetSymbolAddress((void**)&wvl, g_wvl);
    cudaGetSymbolAddress((void**)&wkh, g_wkh);
    cudaGetSymbolAddress((void**)&wkl, g_wkl);
    cudaGetSymbolAddress((void**)&wnh, g_wnh);
    cudaGetSymbolAddress((void**)&wnl, g_wnl);
    cudaGetSymbolAddress((void**)&weh, g_weh);
    cudaGetSymbolAddress((void**)&wel, g_wel);

    // opt-in to 86 KB dynamic smem (immediate API, idempotent, capture-safe)
    cudaFuncSetAttribute(mmagemm128<false, false, false>,
                         cudaFuncAttributeMaxDynamicSharedMemorySize, SMEM_DYN);
    cudaFuncSetAttribute(mmagemm128<false, false, true>,
                         cudaFuncAttributeMaxDynamicSharedMemorySize, SMEM_DYN);
    cudaFuncSetAttribute(mmagemm128<false, true, false>,
                         cudaFuncAttributeMaxDynamicSharedMemorySize, SMEM_DYN);
    cudaFuncSetAttribute(mmagemm128<true, true, false>,
                         cudaFuncAttributeMaxDynamicSharedMemorySize, SMEM_DYN);

    const float qscale = 0.17677669529663687f;   // 1/sqrt(32)

    // 0) pre-split all weights into bf16 hi/lo
    convw_kernel<<<256, 256>>>(Wq, Wv, Wk, Wn, We);

    // 1) q (scaled) and v projections. q must precede k-GEMM (SFUSE reads g_q).
    mmagemm128<false, false, false><<<dim3(8, 2), 256, SMEM_DYN>>>(node, wqh, wql, bq, qb, qscale);
    mmagemm128<false, false, false><<<dim3(8, 2), 256, SMEM_DYN>>>(node, wvh, wvl, bv, vb, 1.f);

    // 2) k projection + fused scores -> g_k, g_S
    mmagemm128<false, false, true><<<dim3(1024, 2), 256, SMEM_DYN>>>(edge, wkh, wkl, bk, kb, 1.f);

    // 3) dual softmax + diag fix + decay -> message; then nh = msg @ v
    msg_nh_kernel<<<64, 256>>>(dist, mask, lam);

    // 4) node output: mish(nh @ Wn^T + bn) -> out[0 : 262144)
    mmagemm128<false, true, false><<<dim3(8, 2), 256, SMEM_DYN>>>(nhb, wnh, wnl, bn, out, 1.f);

    // 5) edge output: mish((msg .* k) @ We^T + be) -> out[262144 : )
    mmagemm128<true, true, false><<<dim3(1024, 2), 256, SMEM_DYN>>>(kb, weh, wel, be, out + 262144, 1.f);
}